// round 3
// baseline (speedup 1.0000x reference)
#include <cuda_runtime.h>
#include <cuda_bf16.h>
#include <cuda_fp16.h>
#include <cuda_fp8.h>
#include <cstdint>

#define N_ROWS      12288        // L1_INPUT_SIZE
#define N_COLS      1030         // L1_OUTPUT_SIZE
#define HID         1024
#define STRIDE8     1152         // padded fp8 row stride bytes (128B multiple)
#define BATCH       8192
#define NFEAT       32
#define L2IN        2048
#define W_SCALE     128.0f       // weight scale into e4m3 normal range
#define INV_SCALE   0.0078125f   // 1/128
#define PSQT_K      0.08f        // 0.5 / (400/64)
#define GPR         258          // groups of 4 cols converted per row (covers 1030 + pad to 1032)

// fp8(e4m3) copy of W1*128, 128B-aligned padded rows (module-static, no runtime alloc)
__device__ __align__(128) unsigned char g_W1f8[(size_t)N_ROWS * STRIDE8];

// ---------------------------------------------------------------------------
// W1 fp32 -> fp8 conversion (runs every launch; deterministic)
// one thread per 4 columns; float2 reads, u32 (fp8x4) write into padded layout
// ---------------------------------------------------------------------------
__global__ void convert_kernel(const float* __restrict__ W1) {
    int gid = blockIdx.x * blockDim.x + threadIdx.x;
    if (gid >= N_ROWS * GPR) return;
    const int r   = gid / GPR;
    const int g   = gid - r * GPR;
    const int col = g * 4;
    const float* src = W1 + (size_t)r * N_COLS + col;

    float4 w;
    if (col + 4 <= N_COLS) {
        const float2 a = *reinterpret_cast<const float2*>(src);
        const float2 b = *reinterpret_cast<const float2*>(src + 2);
        w = make_float4(a.x, a.y, b.x, b.y);
    } else {
        w.x = (col + 0 < N_COLS) ? src[0] : 0.f;
        w.y = (col + 1 < N_COLS) ? src[1] : 0.f;
        w.z = (col + 2 < N_COLS) ? src[2] : 0.f;
        w.w = (col + 3 < N_COLS) ? src[3] : 0.f;
    }
    const __nv_fp8x2_storage_t lo =
        __nv_cvt_float2_to_fp8x2(make_float2(w.x * W_SCALE, w.y * W_SCALE),
                                 __NV_SATFINITE, __NV_E4M3);
    const __nv_fp8x2_storage_t hi =
        __nv_cvt_float2_to_fp8x2(make_float2(w.z * W_SCALE, w.w * W_SCALE),
                                 __NV_SATFINITE, __NV_E4M3);
    const uint32_t packed = (uint32_t)lo | ((uint32_t)hi << 16);
    *reinterpret_cast<uint32_t*>(g_W1f8 + (size_t)r * STRIDE8 + col) = packed;
}

// ---------------------------------------------------------------------------
// unpack u32 (4×e4m3) -> two half2, fused multiply-accumulate with vh
// ---------------------------------------------------------------------------
__device__ __forceinline__ void fma4_fp8(half2& a0, half2& a1, uint32_t w, half2 vh) {
    uint32_t h0, h1;
    asm("{\n\t"
        ".reg .b16 lo, hi;\n\t"
        "mov.b32 {lo, hi}, %2;\n\t"
        "cvt.rn.f16x2.e4m3x2 %0, lo;\n\t"
        "cvt.rn.f16x2.e4m3x2 %1, hi;\n\t"
        "}" : "=r"(h0), "=r"(h1) : "r"(w));
    a0 = __hfma2(*reinterpret_cast<half2*>(&h0), vh, a0);
    a1 = __hfma2(*reinterpret_cast<half2*>(&h1), vh, a1);
}

// ---------------------------------------------------------------------------
// Main fused kernel: one CTA per batch row, 128 threads.
// Threads 0..63 own the x side (16 cols each), threads 64..127 the y side.
// ---------------------------------------------------------------------------
__global__ __launch_bounds__(128)
void fwd_kernel(const int*   __restrict__ x,
                const int*   __restrict__ y,
                const float* __restrict__ v,
                const int*   __restrict__ s,
                const float* __restrict__ b1,
                const float* __restrict__ W2,
                const float* __restrict__ b2,
                float*       __restrict__ out)
{
    __shared__ int   soff[2][NFEAT];   // precomputed row byte-offsets (idx * STRIDE8)
    __shared__ float svf[NFEAT];
    __shared__ half2 svh[NFEAT];
    __shared__ int   ss_sh;
    __shared__ float red[4];

    const int b = blockIdx.x;
    const int t = threadIdx.x;

    if (t < NFEAT) {
        soff[0][t] = x[b * NFEAT + t] * STRIDE8;
        const float vv = v[b * NFEAT + t];
        svf[t] = vv;
        svh[t] = __float2half2_rn(vv);
    } else if (t < 2 * NFEAT) {
        soff[1][t - NFEAT] = y[b * NFEAT + (t - NFEAT)] * STRIDE8;
    } else if (t == 64) {
        ss_sh = s[b];
    }
    __syncthreads();

    const int side = t >> 6;           // 0 = x, 1 = y
    const int lane = t & 63;
    const int col0 = lane * 16;        // 16 fp8 columns per thread
    const unsigned char* basep = g_W1f8 + col0;
    const int* offs = soff[side];

    half2 acc[8];
#pragma unroll
    for (int j = 0; j < 8; ++j) acc[j] = __float2half2_rn(0.f);

#pragma unroll 4
    for (int a = 0; a < NFEAT; ++a) {
        const uint4 w = *reinterpret_cast<const uint4*>(basep + offs[a]);
        const half2 vh = svh[a];
        fma4_fp8(acc[0], acc[1], w.x, vh);
        fma4_fp8(acc[2], acc[3], w.y, vh);
        fma4_fp8(acc[4], acc[5], w.z, vh);
        fma4_fp8(acc[6], acc[7], w.w, vh);
    }

    // ---- epilogue: relu(acc/128 + b1) dot W2[ss] for this thread's 16 cols ----
    const int ss = ss_sh;
    const float* w2seg = W2 + (size_t)ss * L2IN + side * HID + col0;
    const float* b1seg = b1 + col0;

    float local = 0.f;
#pragma unroll
    for (int j = 0; j < 4; ++j) {
        const float4 bb = reinterpret_cast<const float4*>(b1seg)[j];
        const float4 ww = reinterpret_cast<const float4*>(w2seg)[j];
        const float2 f0 = __half22float2(acc[2 * j]);
        const float2 f1 = __half22float2(acc[2 * j + 1]);
        local = fmaf(fmaxf(fmaf(f0.x, INV_SCALE, bb.x), 0.f), ww.x, local);
        local = fmaf(fmaxf(fmaf(f0.y, INV_SCALE, bb.y), 0.f), ww.y, local);
        local = fmaf(fmaxf(fmaf(f1.x, INV_SCALE, bb.z), 0.f), ww.z, local);
        local = fmaf(fmaxf(fmaf(f1.y, INV_SCALE, bb.w), 0.f), ww.w, local);
    }

    // ---- psqt term: (x2 - y2) * PSQT_K ; b1 cancels in the difference ----
    // threads 0..31 -> x side feature t ; threads 32..63 -> y side feature t-32
    if (t < 64) {
        const int a  = t & 31;
        const int sp = t >> 5;
        const unsigned char wb = g_W1f8[(size_t)soff[sp][a] + HID + ss];
        const float w = __half2float(
            __nv_cvt_fp8_to_halfraw((__nv_fp8_storage_t)wb, __NV_E4M3));
        const float p = svf[a] * w * (PSQT_K * INV_SCALE);
        local += (sp == 0) ? p : -p;
    }

    // ---- block reduction ----
#pragma unroll
    for (int o = 16; o > 0; o >>= 1)
        local += __shfl_down_sync(0xffffffffu, local, o);
    if ((t & 31) == 0) red[t >> 5] = local;
    __syncthreads();
    if (t == 0) {
        float c = red[0] + red[1] + red[2] + red[3] + b2[ss];
        out[b] = 1.0f / (1.0f + expf(-c));
    }
}

// ---------------------------------------------------------------------------
extern "C" void kernel_launch(void* const* d_in, const int* in_sizes, int n_in,
                              void* d_out, int out_size)
{
    const int*   x  = (const int*)  d_in[0];
    const int*   y  = (const int*)  d_in[1];
    const float* v  = (const float*)d_in[2];
    const int*   s  = (const int*)  d_in[3];
    const float* W1 = (const float*)d_in[4];
    const float* b1 = (const float*)d_in[5];
    const float* W2 = (const float*)d_in[6];
    const float* b2 = (const float*)d_in[7];
    float* out = (float*)d_out;

    const int total = N_ROWS * GPR;
    convert_kernel<<<(total + 255) / 256, 256>>>(W1);
    fwd_kernel<<<BATCH, 128>>>(x, y, v, s, b1, W2, b2, out);
}